// round 3
// baseline (speedup 1.0000x reference)
#include <cuda_runtime.h>
#include <cuda_bf16.h>
#include <math.h>

#define T_SEQ 8192
#define EMB   512
#define HID   2048
#define NC    256
#define R4    8192      // 4*HID stacked gate rows (f,i,c,o)
#define WCOLS 2560      // EMB+HID
#define NB    128       // persistent CTAs (1 per SM, 128 <= 148)
#define HPB   16        // hidden units per CTA

// SMEM-resident weight rows per CTA (of its 64 gate rows)
#define WS_ROWS 48
#define LSTM_SMEM (WS_ROWS * HID * 2 + HID * 4 + 64 * 4)   // 196608 + 8192 + 256

// ---------------- device scratch --------------------------------------------
__device__ float         g_X[(size_t)T_SEQ * EMB];      // 16 MB
__device__ float         g_Gx[(size_t)T_SEQ * R4];      // 256 MB: W_x@x_t + b
__device__ float         g_Hall[(size_t)T_SEQ * HID];   // 64 MB: all h_t
__device__ __nv_bfloat16 g_Whh[(size_t)R4 * HID];       // 32 MB: packed W_h bf16
__device__ float         g_h[2][HID];                   // double-buffered h
__device__ int           g_flag[NB];                    // per-CTA step flags

__device__ __forceinline__ float bflo(unsigned u) { return __uint_as_float(u << 16); }
__device__ __forceinline__ float bfhi(unsigned u) { return __uint_as_float(u & 0xffff0000u); }

// ---------------- phase -1: reset flags + h0 --------------------------------
__global__ void reset_kernel() {
    int tid = threadIdx.x;
    if (tid < NB) g_flag[tid] = 0;
    for (int i = tid; i < 2 * HID; i += blockDim.x) g_h[0][i] = 0.f, g_h[1][i] = 0.f;
}

// ---------------- phase 0a: pack hidden-part weights to bf16 ----------------
// packed row p = cta*64 + lr;  lr: gate = lr>>4 (f,i,c,o), jj = lr&15
__global__ void pack_wh(const float* __restrict__ Wf, const float* __restrict__ Wi,
                        const float* __restrict__ Wc, const float* __restrict__ Wo) {
    int p = blockIdx.x;
    int b = p >> 6, lr = p & 63, gate = lr >> 4, jj = lr & 15;
    const float* W = gate == 0 ? Wf : gate == 1 ? Wi : gate == 2 ? Wc : Wo;
    const float* src = W + (size_t)(b * HPB + jj) * WCOLS + EMB;
    __nv_bfloat16* dst = g_Whh + (size_t)p * HID;
    for (int c = threadIdx.x; c < HID; c += blockDim.x)
        dst[c] = __float2bfloat16(src[c]);
}

// ---------------- phase 0b: gather embeddings -------------------------------
__global__ void gather_kernel(const int* __restrict__ seq,
                              const float* __restrict__ emb) {
    int t = blockIdx.x;
    int c = seq[t];
    for (int e = threadIdx.x; e < EMB; e += blockDim.x)
        g_X[(size_t)t * EMB + e] = emb[(size_t)c * EMB + e];
}

// ---------------- phase 1: Gx[t][r] = W_x @ x_t + b (fp32, exact) -----------
__global__ void __launch_bounds__(256) gx_gemm(
    const float* __restrict__ Wf, const float* __restrict__ Wi,
    const float* __restrict__ Wc, const float* __restrict__ Wo,
    const float* __restrict__ bf, const float* __restrict__ bi,
    const float* __restrict__ bc, const float* __restrict__ bo) {
    const int r0 = blockIdx.x * 64;
    const int t0 = blockIdx.y * 64;
    const int gate = r0 >> 11;
    const int j0 = r0 & (HID - 1);
    const float* W    = gate == 0 ? Wf : gate == 1 ? Wi : gate == 2 ? Wc : Wo;
    const float* bias = gate == 0 ? bf : gate == 1 ? bi : gate == 2 ? bc : bo;

    __shared__ float As[16][64];
    __shared__ float Bs[16][64];
    const int tid = threadIdx.x;
    const int tx = tid & 15, ty = tid >> 4;

    float acc[4][4];
#pragma unroll
    for (int i = 0; i < 4; i++)
#pragma unroll
        for (int j = 0; j < 4; j++) acc[i][j] = 0.f;

    for (int kk = 0; kk < EMB; kk += 16) {
#pragma unroll
        for (int l = tid; l < 1024; l += 256) {
            int k = l & 15, i = l >> 4;
            As[k][i] = g_X[(size_t)(t0 + i) * EMB + kk + k];
            Bs[k][i] = W[(size_t)(j0 + i) * WCOLS + kk + k];
        }
        __syncthreads();
#pragma unroll
        for (int k = 0; k < 16; k++) {
            float a[4], bb[4];
#pragma unroll
            for (int i = 0; i < 4; i++) a[i]  = As[k][ty * 4 + i];
#pragma unroll
            for (int j = 0; j < 4; j++) bb[j] = Bs[k][tx * 4 + j];
#pragma unroll
            for (int i = 0; i < 4; i++)
#pragma unroll
                for (int j = 0; j < 4; j++) acc[i][j] += a[i] * bb[j];
        }
        __syncthreads();
    }
#pragma unroll
    for (int i = 0; i < 4; i++)
#pragma unroll
        for (int j = 0; j < 4; j++)
            g_Gx[(size_t)(t0 + ty * 4 + i) * R4 + r0 + tx * 4 + j] =
                acc[i][j] + bias[j0 + tx * 4 + j];
}

// ---------------- phase 2: persistent LSTM recurrence (SMEM weights) --------
__global__ void __launch_bounds__(256, 1) lstm_rec(float* __restrict__ out) {
    extern __shared__ char smem_raw[];
    __nv_bfloat16* wsm  = (__nv_bfloat16*)smem_raw;                 // 48 rows x 2048
    float*         sh   = (float*)(smem_raw + WS_ROWS * HID * 2);   // h staging
    float*         gsum = sh + HID;                                 // 64 row sums

    const int b = blockIdx.x;
    const int tid = threadIdx.x;
    const int lane = tid & 31, w = tid >> 5;

    // preload this CTA's 48 SMEM weight rows (warp w's local rows i=0..5)
    for (int r = 0; r < WS_ROWS; r++) {
        int w8 = r / 6, i = r % 6;
        int p = b * 64 + w8 * 8 + i;
        const uint4* src = (const uint4*)(g_Whh + (size_t)p * HID);
        uint4* dst = (uint4*)(wsm + r * HID);
        dst[tid] = src[tid];      // 256 x 16B = 4096B per row
    }
    __syncthreads();

    // per-warp row pointers: rows 0..5 from SMEM, 6..7 from L2
    const uint4* wp[8];
#pragma unroll
    for (int i = 0; i < 8; i++) {
        if (i < 6) wp[i] = (const uint4*)(wsm + (w * 6 + i) * HID);
        else       wp[i] = (const uint4*)(g_Whh + (size_t)(b * 64 + w * 8 + i) * HID);
    }

    float c_reg = 0.f, h_last = 0.f;
    const float4* sh4 = (const float4*)sh;
    float4* shd = (float4*)sh;

    for (int t = 0; t < T_SEQ; t++) {
        // prefetch this CTA's Gx contributions (independent of h)
        float rgf = 0.f, rgi = 0.f, rgc = 0.f, rgo = 0.f;
        if (tid < HPB) {
            const float* gx = g_Gx + (size_t)t * R4 + b * HPB + tid;
            rgf = gx[0];
            rgi = gx[HID];
            rgc = gx[2 * HID];
            rgo = gx[3 * HID];
        }

        // wait for h_t from all CTAs (distributed flag barrier)
        if (tid < NB) {
            int s;
            do {
                asm volatile("ld.acquire.gpu.s32 %0, [%1];"
                             : "=r"(s) : "l"(g_flag + tid) : "memory");
            } while (s < t);
        }
        __syncthreads();

        // stage h_t into SMEM
        {
            const float4* hsrc = (const float4*)g_h[t & 1];
            shd[tid]       = hsrc[tid];
            shd[tid + 256] = hsrc[tid + 256];
        }
        __syncthreads();

        // 8 gate rows per warp, 64 cols per lane
        float acc[8];
#pragma unroll
        for (int i = 0; i < 8; i++) acc[i] = 0.f;
#pragma unroll 4
        for (int m = 0; m < 8; m++) {
            const int base = lane + 32 * m;
            float4 ha = sh4[base * 2];
            float4 hb = sh4[base * 2 + 1];
#pragma unroll
            for (int i = 0; i < 8; i++) {
                uint4 wv = wp[i][base];
                float s;
                s  = bflo(wv.x) * ha.x + bfhi(wv.x) * ha.y;
                s += bflo(wv.y) * ha.z + bfhi(wv.y) * ha.w;
                s += bflo(wv.z) * hb.x + bfhi(wv.z) * hb.y;
                s += bflo(wv.w) * hb.z + bfhi(wv.w) * hb.w;
                acc[i] += s;
            }
        }
#pragma unroll
        for (int i = 0; i < 8; i++) {
            float v = acc[i];
#pragma unroll
            for (int s = 16; s; s >>= 1) v += __shfl_xor_sync(0xffffffffu, v, s);
            if (lane == 0) gsum[w * 8 + i] = v;
        }
        __syncthreads();

        if (tid < HPB) {
            float gf = gsum[tid]      + rgf;
            float gi = gsum[16 + tid] + rgi;
            float gc = gsum[32 + tid] + rgc;
            float go = gsum[48 + tid] + rgo;
            float f  = 1.f / (1.f + expf(-gf));
            float ii = 1.f / (1.f + expf(-gi));
            float ct = tanhf(gc);
            float o  = 1.f / (1.f + expf(-go));
            c_reg = f * c_reg + ii * ct;
            float hn = o * tanhf(c_reg);
            h_last = hn;
            g_h[(t + 1) & 1][b * HPB + tid] = hn;
            g_Hall[(size_t)t * HID + b * HPB + tid] = hn;
        }
        __syncthreads();
        if (tid == 0) {
            __threadfence();
            asm volatile("st.release.gpu.s32 [%0], %1;"
                         :: "l"(g_flag + b), "r"(t + 1) : "memory");
        }
    }

    if (tid < HPB) {
        out[(size_t)T_SEQ * NC + b * HPB + tid]       = h_last;   // final h
        out[(size_t)T_SEQ * NC + HID + b * HPB + tid] = c_reg;    // final c
    }
}

// ---------------- phase 3: Y = Hall @ W_y^T + b_y (fp32, exact) -------------
__global__ void __launch_bounds__(256) y_gemm(
    const float* __restrict__ Wy, const float* __restrict__ by,
    float* __restrict__ out) {
    const int n0 = blockIdx.x * 64;
    const int t0 = blockIdx.y * 64;
    __shared__ float As[16][64];
    __shared__ float Bs[16][64];
    const int tid = threadIdx.x;
    const int tx = tid & 15, ty = tid >> 4;

    float acc[4][4];
#pragma unroll
    for (int i = 0; i < 4; i++)
#pragma unroll
        for (int j = 0; j < 4; j++) acc[i][j] = 0.f;

    for (int kk = 0; kk < HID; kk += 16) {
#pragma unroll
        for (int l = tid; l < 1024; l += 256) {
            int k = l & 15, i = l >> 4;
            As[k][i] = g_Hall[(size_t)(t0 + i) * HID + kk + k];
            Bs[k][i] = Wy[(size_t)(n0 + i) * HID + kk + k];
        }
        __syncthreads();
#pragma unroll
        for (int k = 0; k < 16; k++) {
            float a[4], bb[4];
#pragma unroll
            for (int i = 0; i < 4; i++) a[i]  = As[k][ty * 4 + i];
#pragma unroll
            for (int j = 0; j < 4; j++) bb[j] = Bs[k][tx * 4 + j];
#pragma unroll
            for (int i = 0; i < 4; i++)
#pragma unroll
                for (int j = 0; j < 4; j++) acc[i][j] += a[i] * bb[j];
        }
        __syncthreads();
    }
#pragma unroll
    for (int i = 0; i < 4; i++)
#pragma unroll
        for (int j = 0; j < 4; j++)
            out[(size_t)(t0 + ty * 4 + i) * NC + n0 + tx * 4 + j] =
                acc[i][j] + by[n0 + tx * 4 + j];
}

// ---------------- launch ----------------------------------------------------
extern "C" void kernel_launch(void* const* d_in, const int* in_sizes, int n_in,
                              void* d_out, int out_size) {
    const int*   seq = (const int*)  d_in[0];
    const float* emb = (const float*)d_in[1];
    const float* Wf  = (const float*)d_in[2];
    const float* bf  = (const float*)d_in[3];
    const float* Wi  = (const float*)d_in[4];
    const float* bi  = (const float*)d_in[5];
    const float* Wo  = (const float*)d_in[6];
    const float* bo  = (const float*)d_in[7];
    const float* Wc  = (const float*)d_in[8];
    const float* bc  = (const float*)d_in[9];
    const float* Wy  = (const float*)d_in[10];
    const float* by  = (const float*)d_in[11];
    float* out = (float*)d_out;

    static bool attr_done = false;
    if (!attr_done) {
        cudaFuncSetAttribute(lstm_rec, cudaFuncAttributeMaxDynamicSharedMemorySize,
                             LSTM_SMEM);
        attr_done = true;
    }

    reset_kernel<<<1, 256>>>();
    pack_wh<<<R4, 256>>>(Wf, Wi, Wc, Wo);
    gather_kernel<<<T_SEQ, 128>>>(seq, emb);

    dim3 g1(R4 / 64, T_SEQ / 64);
    gx_gemm<<<g1, 256>>>(Wf, Wi, Wc, Wo, bf, bi, bc, bo);

    lstm_rec<<<NB, 256, LSTM_SMEM>>>(out);

    dim3 g2(NC / 64, T_SEQ / 64);
    y_gemm<<<g2, 256>>>(Wy, by, out);
}